// round 7
// baseline (speedup 1.0000x reference)
#include <cuda_runtime.h>
#include <cstdint>

#define N_MAX 4096
#define W_MAX 128              // words per row (N_MAX/32)
#define FULLMASK 0xFFFFFFFFu

// Static scratch (allocations forbidden).
__device__ float4   g_pos4[N_MAX];
__device__ int      g_count[N_MAX];
__device__ int      g_offset[N_MAX];
__device__ int      g_done;
__device__ unsigned g_mask[N_MAX * W_MAX];   // 2 MB ballot bitmap, row-major words

__device__ __forceinline__ int warp_inc_scan(int v, int lane) {
#pragma unroll
    for (int off = 1; off < 32; off <<= 1) {
        int u = __shfl_up_sync(FULLMASK, v, off);
        if (lane >= off) v += u;
    }
    return v;
}

// ---------------------------------------------------------------------------
// Pack pos (N,3)+batch into float4; pad [n, n_pad) with per-row-distinct
// sentinel batch. Zeroes g_count (all rows) and g_done (graph-replay safe).
__global__ void pack_kernel(const float* __restrict__ pos,
                            const int* __restrict__ batch, int n, int n_pad) {
    int i = blockIdx.x * blockDim.x + threadIdx.x;
    if (i == 0) g_done = 0;
    if (i < N_MAX) g_count[i] = 0;
    if (i < n) {
        float4 p;
        p.x = pos[3 * i + 0];
        p.y = pos[3 * i + 1];
        p.z = pos[3 * i + 2];
        p.w = __int_as_float(batch[i]);
        g_pos4[i] = p;
    } else if (i < n_pad) {
        g_pos4[i] = make_float4(1e9f, 1e9f, 1e9f, __int_as_float(-2 - i));
    }
}

// ---------------------------------------------------------------------------
// Fused pass A:
//   (1) each block writes its grid-stride slice of the output init
//       (edge_index=-1, weight/vec=0) -- overlaps with tile compute
//   (2) symmetric 32x32 tile evaluation + fused row counting (atomics)
//   (3) last block to finish performs the exclusive offset scan in-kernel
__global__ void mask_fused_kernel(float* __restrict__ out, int nw, int mp) {
    int I = blockIdx.y;
    int wslot = threadIdx.x >> 5;
    int J = blockIdx.x * 8 + wslot;
    int lane = threadIdx.x & 31;
    int nblocks = gridDim.x * gridDim.y;
    int bid = blockIdx.y * gridDim.x + blockIdx.x;

    // --- (1) output init slice (fire-and-forget stores) ---
    {
        long long total4 = (6LL * mp) >> 2;          // mp % 4 == 0
        long long stride = (long long)nblocks * blockDim.x;
        for (long long e = (long long)bid * blockDim.x + threadIdx.x;
             e < total4; e += stride) {
            long long idx = e << 2;
            float v = (idx < 2LL * mp) ? -1.0f : 0.0f;
            *reinterpret_cast<float4*>(out + idx) = make_float4(v, v, v, v);
        }
    }

    // --- (2) tile evaluation ---
    __shared__ float4 sh[8][32];
    bool valid = (J < nw) & (J >= I);
    if (valid) {
        float4 pi = g_pos4[I * 32 + lane];
        sh[wslot][lane] = g_pos4[J * 32 + lane];
        __syncwarp();
        int ib = __float_as_int(pi.w);

        unsigned myword = 0;
        if (I == J) {
#pragma unroll 8
            for (int k = 0; k < 32; k++) {
                float4 q = sh[wslot][k];
                float dx = __fadd_rn(pi.x, -q.x);
                float dy = __fadd_rn(pi.y, -q.y);
                float dz = __fadd_rn(pi.z, -q.z);
                float d2 = __fadd_rn(__fadd_rn(__fmul_rn(dx, dx), __fmul_rn(dy, dy)),
                                     __fmul_rn(dz, dz));
                bool p = (ib == __float_as_int(q.w)) & (d2 < 25.0f) & (k != lane);
                if (p) p = (__fsqrt_rn(d2) < 5.0f);
                myword |= ((unsigned)p) << k;
            }
            g_mask[(size_t)(I * 32 + lane) * nw + J] = myword;
            int pc = __popc(myword);
            if (pc) atomicAdd(&g_count[I * 32 + lane], pc);
        } else {
            unsigned tword = 0;
#pragma unroll 8
            for (int k = 0; k < 32; k++) {
                float4 q = sh[wslot][k];
                float dx = __fadd_rn(pi.x, -q.x);
                float dy = __fadd_rn(pi.y, -q.y);
                float dz = __fadd_rn(pi.z, -q.z);
                float d2 = __fadd_rn(__fadd_rn(__fmul_rn(dx, dx), __fmul_rn(dy, dy)),
                                     __fmul_rn(dz, dz));
                bool p = (ib == __float_as_int(q.w)) & (d2 < 25.0f);
                if (p) p = (__fsqrt_rn(d2) < 5.0f);
                unsigned bal = __ballot_sync(FULLMASK, p);  // bit m = pred(I*32+m, j)
                myword |= ((unsigned)p) << k;
                if (lane == k) tword = bal;                 // row J*32+k, word I
            }
            g_mask[(size_t)(I * 32 + lane) * nw + J] = myword;
            g_mask[(size_t)(J * 32 + lane) * nw + I] = tword;
            int pc0 = __popc(myword);
            int pc1 = __popc(tword);
            if (pc0) atomicAdd(&g_count[I * 32 + lane], pc0);
            if (pc1) atomicAdd(&g_count[J * 32 + lane], pc1);
        }
    }

    // --- (3) last block performs the offset scan ---
    __shared__ int s_last;
    __shared__ int wsum[8];
    __threadfence();
    __syncthreads();
    if (threadIdx.x == 0)
        s_last = (atomicAdd(&g_done, 1) == nblocks - 1) ? 1 : 0;
    __syncthreads();
    if (s_last) {
        __threadfence();                 // see all other blocks' count atomics
        int t = threadIdx.x;             // 256 threads x 16 counts = 4096
        int tl = t & 31, tw = t >> 5;
        int v[16];
#pragma unroll
        for (int k = 0; k < 4; k++) {
            int4 c = reinterpret_cast<int4*>(g_count)[t * 4 + k];
            v[k * 4 + 0] = c.x; v[k * 4 + 1] = c.y;
            v[k * 4 + 2] = c.z; v[k * 4 + 3] = c.w;
        }
        int tot = 0;
        int pre[16];
#pragma unroll
        for (int k = 0; k < 16; k++) { pre[k] = tot; tot += v[k]; }
        int inc = warp_inc_scan(tot, tl);
        if (tl == 31) wsum[tw] = inc;
        __syncthreads();
        if (tw == 0) {
            int x = (tl < 8) ? wsum[tl] : 0;
            x = warp_inc_scan(x, tl);
            if (tl < 8) wsum[tl] = x;
        }
        __syncthreads();
        int base = (tw ? wsum[tw - 1] : 0) + (inc - tot);
#pragma unroll
        for (int k = 0; k < 4; k++) {
            int4 o;
            o.x = base + pre[k * 4 + 0];
            o.y = base + pre[k * 4 + 1];
            o.z = base + pre[k * 4 + 2];
            o.w = base + pre[k * 4 + 3];
            reinterpret_cast<int4*>(g_offset)[t * 4 + k] = o;
        }
    }
}

// ---------------------------------------------------------------------------
// Pass B: expand persisted masks (diagonal pre-cleared). One warp per row.
__global__ void fill_kernel(float* __restrict__ out, int n, int mp, int nw) {
    int row = (blockIdx.x * blockDim.x + threadIdx.x) >> 5;
    int lane = threadIdx.x & 31;
    if (row >= n) return;
    float4 pi = g_pos4[row];
    const unsigned* mrow = g_mask + (size_t)row * nw;
    int base = g_offset[row];
    float fi = (float)row;
    for (int w0 = 0; w0 < nw; w0 += 32) {
        unsigned m = mrow[w0 + lane];
        int pc = __popc(m);
        int inc = warp_inc_scan(pc, lane);
        int tot = __shfl_sync(FULLMASK, inc, 31);
        int slot = base + inc - pc;
        while (m) {
            int b = __ffs(m) - 1;
            m &= m - 1;
            int j = (w0 + lane) * 32 + b;
            float4 pj = g_pos4[j];
            float dx = __fadd_rn(pi.x, -pj.x);
            float dy = __fadd_rn(pi.y, -pj.y);
            float dz = __fadd_rn(pi.z, -pj.z);
            float d2 = __fadd_rn(__fadd_rn(__fmul_rn(dx, dx), __fmul_rn(dy, dy)),
                                 __fmul_rn(dz, dz));
            if (slot < mp) {
                out[slot]          = fi;
                out[mp + slot]     = (float)j;
                out[2 * mp + slot] = __fsqrt_rn(d2);
                float* v = out + 3 * mp + 3 * slot;
                v[0] = dx; v[1] = dy; v[2] = dz;
            }
            slot++;
        }
        base += tot;
    }
}

// ---------------------------------------------------------------------------
extern "C" void kernel_launch(void* const* d_in, const int* in_sizes, int n_in,
                              void* d_out, int out_size) {
    const float* pos   = (const float*)d_in[0];
    const int*   batch = (const int*)d_in[1];
    float* out = (float*)d_out;

    int n = in_sizes[1];
    if (n > N_MAX) n = N_MAX;
    int n_pad = (n + 31) & ~31;
    int nw = n_pad / 32;
    int mp = out_size / 6;

    pack_kernel<<<(N_MAX + 255) / 256, 256>>>(pos, batch, n, n_pad);

    dim3 mgrid((nw + 7) / 8, nw);
    mask_fused_kernel<<<mgrid, 256>>>(out, nw, mp);

    fill_kernel<<<(n * 32 + 255) / 256, 256>>>(out, n, mp, nw);
}